// round 3
// baseline (speedup 1.0000x reference)
#include <cuda_runtime.h>
#include <math_constants.h>

#define HH 110
#define WW 110
#define OH 96
#define OW 96
#define WSZ 15
#define BATCH 2
#define CH 4
#define TT 2
#define NPLANE (HH*WW)                 // 12100
#define NPIX (BATCH*CH*TT*NPLANE)      // 387200
#define EPSF 1e-8f
#define U_SPEC 1.41421356237e-3f       // sqrt(1e-6+1e-6); TEMPORAL_U identical
#define BIGD 1e18f
#define NB_STATS 232

// Static scratch (no allocation allowed)
__device__ float4 g_pack[NPIX];        // {LL = log(spec+1)*log(temp+1), P = pd+pf-pc, spec, temp}
__device__ float  g_pfv[NPIX];         // pf if valid else NaN
__device__ double g_part[NB_STATS*3];
__device__ float  g_thr;

__device__ __forceinline__ int covf(int i) {
    int lo = max(0, i - 14);
    int hi = min(95, i);
    return hi - lo + 1;
}

__global__ void precompute_stats(const float* __restrict__ pc,
                                 const float* __restrict__ pf,
                                 const float* __restrict__ pd)
{
    double s0 = 0.0, s1 = 0.0, s2 = 0.0;
    for (int idx = blockIdx.x * blockDim.x + threadIdx.x; idx < NPIX;
         idx += gridDim.x * blockDim.x) {
        int pix = idx % NPLANE;
        int p   = idx / NPLANE;        // (b*CH+c)*TT + t
        int bc  = p / TT;
        float vc = pc[idx];
        float vf = pf[idx];
        float vd = pd[bc * NPLANE + pix];
        float spec = fabsf(vc - vf);
        float temp = fabsf(vc - vd);
        float LL = __logf(spec + 1.0f) * __logf(temp + 1.0f);
        float P  = vd + vf - vc;
        g_pack[idx] = make_float4(LL, P, spec, temp);
        bool valid = (vf >= EPSF);
        g_pfv[idx] = valid ? vf : CUDART_NAN_F;
        if (valid) {
            int i = pix / WW, j = pix % WW;
            double w = (double)(covf(i) * covf(j));
            s0 += w;
            s1 += w * (double)vf;
            s2 += w * (double)vf * (double)vf;
        }
    }
    __shared__ double sh[256 * 3];
    int t = threadIdx.x;
    sh[t] = s0; sh[t + 256] = s1; sh[t + 512] = s2;
    __syncthreads();
    for (int s = 128; s > 0; s >>= 1) {
        if (t < s) {
            sh[t] += sh[t + s];
            sh[t + 256] += sh[t + 256 + s];
            sh[t + 512] += sh[t + 512 + s];
        }
        __syncthreads();
    }
    if (t == 0) {
        g_part[blockIdx.x * 3 + 0] = sh[0];
        g_part[blockIdx.x * 3 + 1] = sh[256];
        g_part[blockIdx.x * 3 + 2] = sh[512];
    }
}

__global__ void finalize_thr()
{
    __shared__ double sh[256 * 3];
    int t = threadIdx.x;
    double s0 = 0.0, s1 = 0.0, s2 = 0.0;
    for (int i = t; i < NB_STATS; i += 256) {
        s0 += g_part[i * 3 + 0];
        s1 += g_part[i * 3 + 1];
        s2 += g_part[i * 3 + 2];
    }
    sh[t] = s0; sh[t + 256] = s1; sh[t + 512] = s2;
    __syncthreads();
    for (int s = 128; s > 0; s >>= 1) {
        if (t < s) {
            sh[t] += sh[t + s];
            sh[t + 256] += sh[t + 256 + s];
            sh[t + 512] += sh[t + 512 + s];
        }
        __syncthreads();
    }
    if (t == 0) {
        double cnt = sh[0];
        double m  = sh[256] / cnt;
        double m2 = sh[512] / cnt;
        double v = m2 - m * m;
        if (v < 0.0) v = 0.0;
        g_thr = (float)(2.0 * sqrt(v) / 5.0);
    }
}

// Each thread computes TWO vertically adjacent outputs (oy0, oy0+1), sharing
// the loaded window rows (16-row union instead of 2x15).
__global__ __launch_bounds__(128) void starfm_main(float* __restrict__ out)
{
    int lane = threadIdx.x & 31;
    int wrp  = threadIdx.x >> 5;               // 0..3
    int ox   = blockIdx.x * 32 + lane;
    int oy0  = blockIdx.y * 8 + wrp * 2;       // outputs oy0 and oy0+1
    int bc   = blockIdx.z;                     // b*CH + c
    int base0 = (bc * TT) * NPLANE;            // t=0 plane base

    // Per-output center data (t=0 and t=1 planes)
    float cs[2], ct[2], pfc[2][2];             // [v][t]
#pragma unroll
    for (int v = 0; v < 2; v++) {
        int cidx = (oy0 + v + 7) * WW + (ox + 7);
        float4 a0 = __ldg(&g_pack[base0 + cidx]);
        float4 a1 = __ldg(&g_pack[base0 + NPLANE + cidx]);
        cs[v] = fmaxf(a0.z, a1.z) + U_SPEC;    // max over t at center + SPECTRAL_U
        ct[v] = fmaxf(a0.w, a1.w) + U_SPEC;    // TEMPORAL_U == SPECTRAL_U numerically
        pfc[v][0] = __ldg(&g_pfv[base0 + cidx]);
        pfc[v][1] = __ldg(&g_pfv[base0 + NPLANE + cidx]);
    }
    float thr = g_thr;

    float sumw0 = 0.f, sumwp0 = 0.f;
    float sumw1 = 0.f, sumwp1 = 0.f;

#pragma unroll
    for (int t = 0; t < TT; t++) {
        int bt = base0 + t * NPLANE;
        float pf0 = pfc[0][t];
        float pf1 = pfc[1][t];
        for (int r = 0; r < WSZ + 1; r++) {    // union of both windows' rows
            // dy for output0 is r (valid r<15); for output1 it's r-1 (valid r>0)
            bool en0 = (r != WSZ);
            bool en1 = (r != 0);
            float dys0 = fmaf((float)((r - 7) * (r - 7)), (1.0f / 7.0f), 1.0f);
            float dys1 = fmaf((float)((r - 8) * (r - 8)), (1.0f / 7.0f), 1.0f);
            int rb = bt + (oy0 + r) * WW + ox;
            float dA0 = BIGD, PA0 = 0.f;
            float dA1 = BIGD, PA1 = 0.f;
#pragma unroll
            for (int dx = 0; dx < WSZ; dx++) {
                const float cdx = (float)((dx - 7) * (dx - 7)) * (1.0f / 7.0f);
                float4 pk = __ldg(&g_pack[rb + dx]);
                float pfx = __ldg(&g_pfv[rb + dx]);
                // masks: filt & similar (NaN-compare -> false), edge rows disabled
                bool m0 = en0 && (pk.z < cs[0]) && (pk.w < ct[0]) &&
                          (fabsf(pfx - pf0) < thr);
                bool m1 = en1 && (pk.z < cs[1]) && (pk.w < ct[1]) &&
                          (fabsf(pfx - pf1) < thr);
                float d0 = m0 ? fmaf(pk.x, dys0 + cdx, EPSF) : BIGD;
                float d1 = m1 ? fmaf(pk.x, dys1 + cdx, EPSF) : BIGD;
                float P = pk.y;
                if ((dx & 1) == 0) {
                    dA0 = d0; dA1 = d1; PA0 = P; PA1 = P;
                } else {
                    // 1/dA + 1/d via one rcp each: (dA+d)*rcp(dA*d)
                    float r0 = __fdividef(1.0f, dA0 * d0);
                    sumw0  = fmaf(dA0 + d0, r0, sumw0);
                    sumwp0 = fmaf(fmaf(dA0, P, d0 * PA0), r0, sumwp0);
                    float r1 = __fdividef(1.0f, dA1 * d1);
                    sumw1  = fmaf(dA1 + d1, r1, sumw1);
                    sumwp1 = fmaf(fmaf(dA1, P, d1 * PA1), r1, sumwp1);
                }
                if (dx == WSZ - 1) {           // leftover dx=14
                    float r0 = __fdividef(1.0f, dA0);
                    sumw0 += r0;
                    sumwp0 = fmaf(PA0, r0, sumwp0);
                    float r1 = __fdividef(1.0f, dA1);
                    sumw1 += r1;
                    sumwp1 = fmaf(PA1, r1, sumwp1);
                }
            }
        }
    }
    int ob = bc * (OH * OW) + oy0 * OW + ox;
    out[ob]      = sumwp0 / (sumw0 + EPSF);
    out[ob + OW] = sumwp1 / (sumw1 + EPSF);
}

extern "C" void kernel_launch(void* const* d_in, const int* in_sizes, int n_in,
                              void* d_out, int out_size)
{
    const float* prior_coarse = (const float*)d_in[0]; // (2,4,2,110,110)
    const float* prior_fine   = (const float*)d_in[1]; // (2,4,2,110,110)
    const float* pred_coarse  = (const float*)d_in[2]; // (2,4,110,110)
    float* out = (float*)d_out;                        // (2,4,96,96)

    precompute_stats<<<NB_STATS, 256>>>(prior_coarse, prior_fine, pred_coarse);
    finalize_thr<<<1, 256>>>();
    dim3 grid(OW / 32, OH / 8, BATCH * CH);            // 3 x 12 x 8 = 288 blocks
    starfm_main<<<grid, 128>>>(out);
}

// round 6
// speedup vs baseline: 1.0120x; 1.0120x over previous
#include <cuda_runtime.h>
#include <math_constants.h>

#define HH 110
#define WW 110
#define OH 96
#define OW 96
#define WSZ 15
#define BATCH 2
#define CH 4
#define TT 2
#define NPLANE (HH*WW)                 // 12100
#define NPIX (BATCH*CH*TT*NPLANE)      // 387200
#define NQUAD (NPIX/4)                 // 96800
#define EPSF 1e-8f
#define U_SPEC 1.41421356237e-3f       // sqrt(1e-6+1e-6); TEMPORAL_U identical
#define BIGD 1e18f
#define NB_STATS 379                   // ceil(96800/256)

// Static scratch (no allocation allowed)
__device__ float4 g_pack[NPIX];        // {LL, P, spec, temp}
__device__ float  g_pfv[NPIX];         // pf if valid else NaN
__device__ double g_part[NB_STATS*3];
__device__ float  g_thr;
__device__ int    g_ticket;            // zero-init; reset by finalizer each launch

__device__ __forceinline__ float covf(int i) {
    int lo = max(0, i - 14);
    int hi = min(95, i);
    return (float)(hi - lo + 1);
}

__device__ __forceinline__ float lane_of(const float4& v, int l) {
    return l == 0 ? v.x : l == 1 ? v.y : l == 2 ? v.z : v.w;
}

__global__ __launch_bounds__(256) void precompute_stats(
        const float* __restrict__ pc,
        const float* __restrict__ pf,
        const float* __restrict__ pd)
{
    int t4 = blockIdx.x * blockDim.x + threadIdx.x;  // float4 index
    float s0 = 0.f, s1 = 0.f, s2 = 0.f;

    if (t4 < NQUAD) {
        int idx = t4 * 4;
        int pix = idx % NPLANE;        // multiple of 4 (NPLANE%4==0)
        int p   = idx / NPLANE;        // (b*CH+c)*TT + t
        int bc  = p / TT;
        float4 vc4 = ((const float4*)pc)[t4];
        float4 vf4 = ((const float4*)pf)[t4];
        float4 vd4 = ((const float4*)pd)[(bc * NPLANE + pix) >> 2];
        float4 pv;
        float* pvp = (float*)&pv;
#pragma unroll
        for (int l = 0; l < 4; l++) {
            float vc = lane_of(vc4, l);
            float vf = lane_of(vf4, l);
            float vd = lane_of(vd4, l);
            float spec = fabsf(vc - vf);
            float temp = fabsf(vc - vd);
            float LL = __logf(spec + 1.0f) * __logf(temp + 1.0f);
            float P  = vd + vf - vc;
            g_pack[idx + l] = make_float4(LL, P, spec, temp);
            bool valid = (vf >= EPSF);
            pvp[l] = valid ? vf : CUDART_NAN_F;
            if (valid) {
                int pp = pix + l;
                int i = pp / WW, j = pp % WW;
                float w = covf(i) * covf(j);     // coverage weight (cube multiplicity)
                s0 += w;
                s1 += w * vf;
                s2 += w * vf * vf;
            }
        }
        ((float4*)g_pfv)[t4] = pv;
    }

    // Block reduction (double)
    __shared__ double sh[256 * 3];
    int t = threadIdx.x;
    sh[t] = (double)s0; sh[t + 256] = (double)s1; sh[t + 512] = (double)s2;
    __syncthreads();
    for (int s = 128; s > 0; s >>= 1) {
        if (t < s) {
            sh[t] += sh[t + s];
            sh[t + 256] += sh[t + 256 + s];
            sh[t + 512] += sh[t + 512 + s];
        }
        __syncthreads();
    }
    if (t == 0) {
        g_part[blockIdx.x * 3 + 0] = sh[0];
        g_part[blockIdx.x * 3 + 1] = sh[256];
        g_part[blockIdx.x * 3 + 2] = sh[512];
    }

    // Last-block finalize (threadfence reduction pattern)
    __shared__ bool isLast;
    __threadfence();
    if (t == 0) {
        int old = atomicAdd(&g_ticket, 1);
        isLast = (old == (int)gridDim.x - 1);
    }
    __syncthreads();
    if (isLast) {
        double a0 = 0.0, a1 = 0.0, a2 = 0.0;
        for (int i = t; i < NB_STATS; i += 256) {
            a0 += g_part[i * 3 + 0];
            a1 += g_part[i * 3 + 1];
            a2 += g_part[i * 3 + 2];
        }
        sh[t] = a0; sh[t + 256] = a1; sh[t + 512] = a2;
        __syncthreads();
        for (int s = 128; s > 0; s >>= 1) {
            if (t < s) {
                sh[t] += sh[t + s];
                sh[t + 256] += sh[t + 256 + s];
                sh[t + 512] += sh[t + 512 + s];
            }
            __syncthreads();
        }
        if (t == 0) {
            double cnt = sh[0];
            double m  = sh[256] / cnt;
            double m2 = sh[512] / cnt;
            double v = m2 - m * m;
            if (v < 0.0) v = 0.0;
            g_thr = (float)(2.0 * sqrt(v) / 5.0);
            g_ticket = 0;              // reset for next graph replay
        }
    }
}

// One window-union row for up to two vertically-adjacent outputs.
// EN0: output oy0 active (dy = r);  EN1: output oy0+1 active (dy = r-1).
template<bool EN0, bool EN1>
__device__ __forceinline__ void process_row(
        int rb, float dys0, float dys1,
        float cs0, float ct0, float pf0,
        float cs1, float ct1, float pf1, float thr,
        float& sumw0, float& sumwp0, float& sumw1, float& sumwp1)
{
    float dA0 = BIGD, PA0 = 0.f;
    float dA1 = BIGD, PA1 = 0.f;
#pragma unroll
    for (int dx = 0; dx < WSZ; dx++) {
        const float cdx = (float)((dx - 7) * (dx - 7)) * (1.0f / 7.0f);
        float4 pk = __ldg(&g_pack[rb + dx]);
        float pfx = __ldg(&g_pfv[rb + dx]);
        // shared partial: tshare = LL*cdx + EPS; then d = LL*dys + tshare
        float tshare = fmaf(pk.x, cdx, EPSF);
        float d0 = BIGD, d1 = BIGD;
        if (EN0) {
            bool m0 = (pk.z < cs0) && (pk.w < ct0) && (fabsf(pfx - pf0) < thr);
            d0 = m0 ? fmaf(pk.x, dys0, tshare) : BIGD;
        }
        if (EN1) {
            bool m1 = (pk.z < cs1) && (pk.w < ct1) && (fabsf(pfx - pf1) < thr);
            d1 = m1 ? fmaf(pk.x, dys1, tshare) : BIGD;
        }
        float P = pk.y;
        if ((dx & 1) == 0) {
            dA0 = d0; dA1 = d1; PA0 = P; PA1 = P;
        } else {
            if (EN0) {
                // 1/dA + 1/d via one rcp: (dA+d)*rcp(dA*d)
                float r0 = __fdividef(1.0f, dA0 * d0);
                sumw0  = fmaf(dA0 + d0, r0, sumw0);
                sumwp0 = fmaf(fmaf(dA0, P, d0 * PA0), r0, sumwp0);
            }
            if (EN1) {
                float r1 = __fdividef(1.0f, dA1 * d1);
                sumw1  = fmaf(dA1 + d1, r1, sumw1);
                sumwp1 = fmaf(fmaf(dA1, P, d1 * PA1), r1, sumwp1);
            }
        }
        if (dx == WSZ - 1) {           // leftover dx=14
            if (EN0) {
                float r0 = __fdividef(1.0f, dA0);
                sumw0 += r0;
                sumwp0 = fmaf(PA0, r0, sumwp0);
            }
            if (EN1) {
                float r1 = __fdividef(1.0f, dA1);
                sumw1 += r1;
                sumwp1 = fmaf(PA1, r1, sumwp1);
            }
        }
    }
}

// Each thread computes TWO vertically adjacent outputs (oy0, oy0+1), sharing
// the loaded window rows (16-row union instead of 2x15). Edge rows peeled.
__global__ __launch_bounds__(128) void starfm_main(float* __restrict__ out)
{
    int lane = threadIdx.x & 31;
    int wrp  = threadIdx.x >> 5;               // 0..3
    int ox   = blockIdx.x * 32 + lane;
    int oy0  = blockIdx.y * 8 + wrp * 2;       // outputs oy0 and oy0+1
    int bc   = blockIdx.z;                     // b*CH + c
    int base0 = (bc * TT) * NPLANE;            // t=0 plane base

    float cs[2], ct[2], pfc[2][2];             // [v][t]
#pragma unroll
    for (int v = 0; v < 2; v++) {
        int cidx = (oy0 + v + 7) * WW + (ox + 7);
        float4 a0 = __ldg(&g_pack[base0 + cidx]);
        float4 a1 = __ldg(&g_pack[base0 + NPLANE + cidx]);
        cs[v] = fmaxf(a0.z, a1.z) + U_SPEC;    // max over t at center + SPECTRAL_U
        ct[v] = fmaxf(a0.w, a1.w) + U_SPEC;    // TEMPORAL_U == SPECTRAL_U numerically
        pfc[v][0] = __ldg(&g_pfv[base0 + cidx]);
        pfc[v][1] = __ldg(&g_pfv[base0 + NPLANE + cidx]);
    }
    float thr = g_thr;

    float sumw0 = 0.f, sumwp0 = 0.f;
    float sumw1 = 0.f, sumwp1 = 0.f;

#pragma unroll
    for (int t = 0; t < TT; t++) {
        int bt = base0 + t * NPLANE;
        float pf0 = pfc[0][t];
        float pf1 = pfc[1][t];
        int rb0 = bt + oy0 * WW + ox;

        // r = 0: only output0 (dy0 = 0 -> (0-7)^2)
        process_row<true, false>(rb0,
            fmaf(49.0f, (1.0f / 7.0f), 1.0f), 0.0f,
            cs[0], ct[0], pf0, cs[1], ct[1], pf1, thr,
            sumw0, sumwp0, sumw1, sumwp1);

        // r = 1..14: both outputs
        for (int r = 1; r < WSZ; r++) {
            float dys0 = fmaf((float)((r - 7) * (r - 7)), (1.0f / 7.0f), 1.0f);
            float dys1 = fmaf((float)((r - 8) * (r - 8)), (1.0f / 7.0f), 1.0f);
            process_row<true, true>(rb0 + r * WW, dys0, dys1,
                cs[0], ct[0], pf0, cs[1], ct[1], pf1, thr,
                sumw0, sumwp0, sumw1, sumwp1);
        }

        // r = 15: only output1 (dy1 = 14 -> (15-8)^2)
        process_row<false, true>(rb0 + WSZ * WW,
            0.0f, fmaf(49.0f, (1.0f / 7.0f), 1.0f),
            cs[0], ct[0], pf0, cs[1], ct[1], pf1, thr,
            sumw0, sumwp0, sumw1, sumwp1);
    }

    int ob = bc * (OH * OW) + oy0 * OW + ox;
    out[ob]      = sumwp0 / (sumw0 + EPSF);
    out[ob + OW] = sumwp1 / (sumw1 + EPSF);
}

extern "C" void kernel_launch(void* const* d_in, const int* in_sizes, int n_in,
                              void* d_out, int out_size)
{
    const float* prior_coarse = (const float*)d_in[0]; // (2,4,2,110,110)
    const float* prior_fine   = (const float*)d_in[1]; // (2,4,2,110,110)
    const float* pred_coarse  = (const float*)d_in[2]; // (2,4,110,110)
    float* out = (float*)d_out;                        // (2,4,96,96)

    precompute_stats<<<NB_STATS, 256>>>(prior_coarse, prior_fine, pred_coarse);
    dim3 grid(OW / 32, OH / 8, BATCH * CH);            // 3 x 12 x 8 = 288 blocks
    starfm_main<<<grid, 128>>>(out);
}